// round 5
// baseline (speedup 1.0000x reference)
#include <cuda_runtime.h>
#include <cuda_bf16.h>
#include <cub/cub.cuh>
#include <cstdint>

// ---------------------------------------------------------------------------
// BaseLayerGate: affin = F[65536,1024] @ Wg[64,1024]^T ; greedy balanced
// assignment (64 sequential top-1024 rounds over unassigned tokens);
// outputs: sort_by_expert[65536], input_splits[64]=1024, output_splits[64]=1024,
// routing_probs[65536]=1.0 (straight-through p - sg(p) + 1 is exactly 1).
//
// Packed-key design: per (expert,token) a 48-bit sort key in a uint64:
//   key = sortable(score) << 16 | (token ^ 0xFFFF)
// Descending keys-only segmented sort == descending score, ties -> ascending
// token (jax top_k semantics). Token recovered from low 16 bits.
// ---------------------------------------------------------------------------

static constexpr int N_TOK = 65536;
static constexpr int D     = 1024;
static constexpr int E     = 64;
static constexpr int C     = N_TOK / E;   // 1024
static constexpr int TOTAL = N_TOK * E;   // 4M

__device__ unsigned long long g_keys_a[TOTAL];    // 32 MB (sort ping)
__device__ unsigned long long g_keys_b[TOTAL];    // 32 MB (sort pong)
__device__ int                g_offsets[E + 1];
__device__ unsigned           g_sbe[N_TOK];       // 256 KB
__device__ unsigned char      g_temp[8u << 20];   // 8 MB CUB temp (DoubleBuffer: KBs)

__device__ __forceinline__ unsigned sortable_f32(float f) {
    unsigned u = __float_as_uint(f);
    return u ^ ((u & 0x80000000u) ? 0xFFFFFFFFu : 0x80000000u);
}

// ---------------------------------------------------------------------------
// GEMM: key[e][t] from sum_k F[t][k]*W[e][k]. 128 tokens x 64 experts / block.
// Deterministic ascending-k FMA accumulation.
// ---------------------------------------------------------------------------
__global__ __launch_bounds__(256) void gemm_affin(
    const float* __restrict__ F, const float* __restrict__ W,
    unsigned long long* __restrict__ keys, int* __restrict__ offsets)
{
    __shared__ float As[128][33];
    __shared__ float Ws[64][33];
    const int tid  = threadIdx.x;
    const int tile = blockIdx.x * 128;
    const int tx   = tid & 15;   // experts 4*tx .. 4*tx+3
    const int ty   = tid >> 4;   // tokens  8*ty .. 8*ty+7

    if (blockIdx.x == 0 && tid <= E) offsets[tid] = tid * N_TOK;

    float acc[8][4];
    #pragma unroll
    for (int i = 0; i < 8; ++i)
        #pragma unroll
        for (int j = 0; j < 4; ++j) acc[i][j] = 0.0f;

    for (int k0 = 0; k0 < D; k0 += 32) {
        #pragma unroll
        for (int it = 0; it < 4; ++it) {
            int idx = tid + it * 256;
            int row = idx >> 3, c4 = idx & 7;
            float4 v = *(const float4*)(F + (size_t)(tile + row) * D + k0 + c4 * 4);
            As[row][c4 * 4 + 0] = v.x; As[row][c4 * 4 + 1] = v.y;
            As[row][c4 * 4 + 2] = v.z; As[row][c4 * 4 + 3] = v.w;
        }
        #pragma unroll
        for (int it = 0; it < 2; ++it) {
            int idx = tid + it * 256;
            int row = idx >> 3, c4 = idx & 7;
            float4 v = *(const float4*)(W + (size_t)row * D + k0 + c4 * 4);
            Ws[row][c4 * 4 + 0] = v.x; Ws[row][c4 * 4 + 1] = v.y;
            Ws[row][c4 * 4 + 2] = v.z; Ws[row][c4 * 4 + 3] = v.w;
        }
        __syncthreads();
        #pragma unroll
        for (int kk = 0; kk < 32; ++kk) {
            float w0 = Ws[tx * 4 + 0][kk];
            float w1 = Ws[tx * 4 + 1][kk];
            float w2 = Ws[tx * 4 + 2][kk];
            float w3 = Ws[tx * 4 + 3][kk];
            #pragma unroll
            for (int i = 0; i < 8; ++i) {
                float f = As[ty * 8 + i][kk];
                acc[i][0] = fmaf(f, w0, acc[i][0]);
                acc[i][1] = fmaf(f, w1, acc[i][1]);
                acc[i][2] = fmaf(f, w2, acc[i][2]);
                acc[i][3] = fmaf(f, w3, acc[i][3]);
            }
        }
        __syncthreads();
    }
    #pragma unroll
    for (int j = 0; j < 4; ++j)
        #pragma unroll
        for (int i = 0; i < 8; ++i) {
            unsigned t = (unsigned)(tile + ty * 8 + i);
            unsigned long long key =
                ((unsigned long long)sortable_f32(acc[i][j]) << 16) |
                (unsigned long long)((t ^ 0xFFFFu) & 0xFFFFu);
            keys[(size_t)(tx * 4 + j) * N_TOK + t] = key;
        }
}

// ---------------------------------------------------------------------------
// Greedy sequential selection: single CTA, 1024 threads, 8KB shared bitmask.
// ---------------------------------------------------------------------------
__global__ __launch_bounds__(1024) void greedy_select(
    const unsigned long long* __restrict__ keys, unsigned* __restrict__ sbe)
{
    __shared__ unsigned mask[N_TOK / 32];  // 8 KB
    __shared__ int warp_sums[32];
    const int tid  = threadIdx.x;
    const int lane = tid & 31;
    const int wid  = tid >> 5;

    for (int i = tid; i < N_TOK / 32; i += 1024) mask[i] = 0u;
    __syncthreads();

    for (int e = 0; e < E; ++e) {
        const unsigned long long* ord = keys + (size_t)e * N_TOK;
        int count = 0, pos = 0;
        while (count < C && pos < N_TOK) {
            ulonglong2 a = *(const ulonglong2*)(ord + pos + tid * 4);
            ulonglong2 b = *(const ulonglong2*)(ord + pos + tid * 4 + 2);
            unsigned tk[4];
            tk[0] = (((unsigned)a.x & 0xFFFFu) ^ 0xFFFFu);
            tk[1] = (((unsigned)a.y & 0xFFFFu) ^ 0xFFFFu);
            tk[2] = (((unsigned)b.x & 0xFFFFu) ^ 0xFFFFu);
            tk[3] = (((unsigned)b.y & 0xFFFFu) ^ 0xFFFFu);
            int fl[4], cnt = 0;
            #pragma unroll
            for (int j = 0; j < 4; ++j) {
                fl[j] = 1 - (int)((mask[tk[j] >> 5] >> (tk[j] & 31)) & 1u);
                cnt += fl[j];
            }
            int inc = cnt;
            #pragma unroll
            for (int off = 1; off < 32; off <<= 1) {
                int n = __shfl_up_sync(0xffffffffu, inc, off);
                if (lane >= off) inc += n;
            }
            if (lane == 31) warp_sums[wid] = inc;
            int thr_excl = inc - cnt;
            __syncthreads();
            if (wid == 0) {
                int v = warp_sums[lane];
                #pragma unroll
                for (int off = 1; off < 32; off <<= 1) {
                    int n = __shfl_up_sync(0xffffffffu, v, off);
                    if (lane >= off) v += n;
                }
                warp_sums[lane] = v;
            }
            __syncthreads();
            int warp_excl = wid ? warp_sums[wid - 1] : 0;
            int total     = warp_sums[31];
            int remaining = C - count;
            int r = warp_excl + thr_excl;
            #pragma unroll
            for (int j = 0; j < 4; ++j) {
                if (fl[j]) {
                    if (r < remaining) {
                        sbe[e * C + count + r] = tk[j];
                        atomicOr(&mask[tk[j] >> 5], 1u << (tk[j] & 31));
                    }
                    ++r;
                }
            }
            count += min(total, remaining);
            pos += 4096;
            __syncthreads();
        }
    }
}

// ---------------------------------------------------------------------------
// Output packing variants
// ---------------------------------------------------------------------------
__global__ void pack_full(const unsigned* __restrict__ sbe,
                          float* __restrict__ out, int out_size)
{
    int i = blockIdx.x * blockDim.x + threadIdx.x;
    if (i >= out_size) return;
    float v;
    if (i < N_TOK)                v = (float)sbe[i];
    else if (i < N_TOK + 2 * E)   v = (float)C;   // input/output splits
    else                          v = 1.0f;       // routing probs (exactly 1)
    out[i] = v;
}

__global__ void pack_ones(float* __restrict__ out, int n)
{
    int i = blockIdx.x * blockDim.x + threadIdx.x;
    if (i < n) out[i] = 1.0f;
}

__global__ void pack_splits(float* __restrict__ out, int n)
{
    int i = blockIdx.x * blockDim.x + threadIdx.x;
    if (i < n) out[i] = (float)C;
}

// ---------------------------------------------------------------------------
extern "C" void kernel_launch(void* const* d_in, const int* in_sizes, int n_in,
                              void* d_out, int out_size)
{
    // Disambiguate inputs by element count (features: 67108864, weight: 65536)
    const float* F  = (const float*)d_in[0];
    const float* Wg = (const float*)d_in[1];
    if (n_in >= 2 && in_sizes[0] < in_sizes[1]) {
        F  = (const float*)d_in[1];
        Wg = (const float*)d_in[0];
    }

    unsigned long long* keys_a = nullptr;
    unsigned long long* keys_b = nullptr;
    int*      offsets = nullptr; unsigned* sbe = nullptr;
    unsigned char* temp = nullptr;
    cudaGetSymbolAddress((void**)&keys_a,  g_keys_a);
    cudaGetSymbolAddress((void**)&keys_b,  g_keys_b);
    cudaGetSymbolAddress((void**)&offsets, g_offsets);
    cudaGetSymbolAddress((void**)&sbe,     g_sbe);
    cudaGetSymbolAddress((void**)&temp,    g_temp);

    if (out_size == N_TOK) {
        pack_ones<<<(N_TOK + 255) / 256, 256>>>((float*)d_out, N_TOK);
        return;
    }
    if (out_size == 2 * E || out_size == E) {
        pack_splits<<<1, 256>>>((float*)d_out, out_size);
        return;
    }

    gemm_affin<<<N_TOK / 128, 256>>>(F, Wg, keys_a, offsets);

    // DoubleBuffer overload: temp storage is O(KB), not a full alternate
    // buffer (the R4 bug: non-DoubleBuffer overload wanted ~32MB temp, the
    // clamped call errored out and never sorted).
    cub::DoubleBuffer<unsigned long long> dbuf(keys_a, keys_b);
    size_t temp_bytes = 0;
    cub::DeviceSegmentedRadixSort::SortKeysDescending(
        nullptr, temp_bytes, dbuf, TOTAL, E, offsets, offsets + 1, 0, 48);
    if (temp_bytes > (size_t)(8u << 20)) temp_bytes = (size_t)(8u << 20);
    cub::DeviceSegmentedRadixSort::SortKeysDescending(
        (void*)temp, temp_bytes, dbuf, TOTAL, E, offsets, offsets + 1, 0, 48);

    // Selector is set deterministically at enqueue; same every call/replay.
    greedy_select<<<1, 1024>>>(dbuf.Current(), sbe);

    pack_full<<<(out_size + 255) / 256, 256>>>(sbe, (float*)d_out, out_size);
}

// round 6
// speedup vs baseline: 2.2429x; 2.2429x over previous
#include <cuda_runtime.h>
#include <cuda_bf16.h>
#include <cub/cub.cuh>
#include <cstdint>

// ---------------------------------------------------------------------------
// BaseLayerGate: affin = F[65536,1024] @ Wg[64,1024]^T ; greedy balanced
// assignment; outputs sbe[65536], splits[64]=1024 (x2), probs[65536]=1.0.
//
// Key: (63-e)<<48 | sortable(score)<<16 | token. ONE global descending radix
// sort over bits [16,54) (expert+score). Stability => equal scores keep input
// (ascending-token) order == jax top_k tie semantics. Expert 0 segment first.
// ---------------------------------------------------------------------------

static constexpr int N_TOK = 65536;
static constexpr int D     = 1024;
static constexpr int E     = 64;
static constexpr int C     = N_TOK / E;   // 1024
static constexpr int TOTAL = N_TOK * E;   // 4M

__device__ unsigned long long g_keys_a[TOTAL];    // 32 MB
__device__ unsigned long long g_keys_b[TOTAL];    // 32 MB
__device__ int                g_offsets[E + 1];
__device__ unsigned           g_sbe[N_TOK];
__device__ unsigned char      g_temp[8u << 20];   // 8 MB CUB temp

__device__ __forceinline__ unsigned sortable_u(unsigned u) {
    return u ^ ((u & 0x80000000u) ? 0xFFFFFFFFu : 0x80000000u);
}
__device__ __forceinline__ unsigned long long ffma2(
    unsigned long long a, unsigned long long b, unsigned long long c) {
    unsigned long long d;
    asm("fma.rn.f32x2 %0, %1, %2, %3;" : "=l"(d) : "l"(a), "l"(b), "l"(c));
    return d;
}
__device__ __forceinline__ unsigned long long bcast2(float f) {
    unsigned long long p;
    asm("mov.b64 %0, {%1, %1};" : "=l"(p) : "f"(f));
    return p;
}

// ---------------------------------------------------------------------------
// GEMM: 128 tokens x 64 experts per block, f32x2 dual-pumped FFMA.
// Each half of every packed accumulator keeps the identical ascending-k FMA
// chain (bit-exact vs the scalar version that passed with rel_err 0).
// ---------------------------------------------------------------------------
__global__ __launch_bounds__(256) void gemm_affin(
    const float* __restrict__ F, const float* __restrict__ W,
    unsigned long long* __restrict__ keys, int* __restrict__ offsets)
{
    __shared__ float As[128][33];
    __shared__ float Wst[32][66];   // [kk][expert], even stride -> aligned LDS.64
    const int tid  = threadIdx.x;
    const int tile = blockIdx.x * 128;
    const int tx   = tid & 15;   // experts 4*tx .. 4*tx+3
    const int ty   = tid >> 4;   // tokens  8*ty .. 8*ty+7

    if (blockIdx.x == 0 && tid <= E) offsets[tid] = tid * N_TOK;

    unsigned long long accp[8][2];  // [token i][expert pair]: lo=4tx+2jp, hi=+1
    #pragma unroll
    for (int i = 0; i < 8; ++i) { accp[i][0] = 0ull; accp[i][1] = 0ull; }

    for (int k0 = 0; k0 < D; k0 += 32) {
        #pragma unroll
        for (int it = 0; it < 4; ++it) {
            int idx = tid + it * 256;
            int row = idx >> 3, c4 = idx & 7;
            float4 v = *(const float4*)(F + (size_t)(tile + row) * D + k0 + c4 * 4);
            As[row][c4 * 4 + 0] = v.x; As[row][c4 * 4 + 1] = v.y;
            As[row][c4 * 4 + 2] = v.z; As[row][c4 * 4 + 3] = v.w;
        }
        #pragma unroll
        for (int it = 0; it < 2; ++it) {
            int idx = tid + it * 256;
            int row = idx >> 3, c4 = idx & 7;   // row = expert
            float4 v = *(const float4*)(W + (size_t)row * D + k0 + c4 * 4);
            Wst[c4 * 4 + 0][row] = v.x; Wst[c4 * 4 + 1][row] = v.y;
            Wst[c4 * 4 + 2][row] = v.z; Wst[c4 * 4 + 3][row] = v.w;
        }
        __syncthreads();
        #pragma unroll
        for (int kk = 0; kk < 32; ++kk) {
            unsigned long long wp0 = *(const unsigned long long*)&Wst[kk][tx * 4];
            unsigned long long wp1 = *(const unsigned long long*)&Wst[kk][tx * 4 + 2];
            #pragma unroll
            for (int i = 0; i < 8; ++i) {
                unsigned long long fp = bcast2(As[ty * 8 + i][kk]);
                accp[i][0] = ffma2(fp, wp0, accp[i][0]);
                accp[i][1] = ffma2(fp, wp1, accp[i][1]);
            }
        }
        __syncthreads();
    }
    #pragma unroll
    for (int i = 0; i < 8; ++i) {
        unsigned t = (unsigned)(tile + ty * 8 + i);
        #pragma unroll
        for (int jp = 0; jp < 2; ++jp) {
            unsigned lo, hi;
            asm("mov.b64 {%0, %1}, %2;" : "=r"(lo), "=r"(hi) : "l"(accp[i][jp]));
            int e0 = tx * 4 + 2 * jp;
            unsigned long long k0 =
                ((unsigned long long)(63 - e0) << 48) |
                ((unsigned long long)sortable_u(lo) << 16) | t;
            unsigned long long k1 =
                ((unsigned long long)(63 - (e0 + 1)) << 48) |
                ((unsigned long long)sortable_u(hi) << 16) | t;
            keys[(size_t)e0 * N_TOK + t]       = k0;
            keys[(size_t)(e0 + 1) * N_TOK + t] = k1;
        }
    }
}

// ---------------------------------------------------------------------------
// Greedy sequential selection: single CTA, 1024 threads, 8KB shared bitmask.
// ---------------------------------------------------------------------------
__global__ __launch_bounds__(1024) void greedy_select(
    const unsigned long long* __restrict__ keys, unsigned* __restrict__ sbe)
{
    __shared__ unsigned mask[N_TOK / 32];  // 8 KB
    __shared__ int warp_sums[32];
    const int tid  = threadIdx.x;
    const int lane = tid & 31;
    const int wid  = tid >> 5;

    for (int i = tid; i < N_TOK / 32; i += 1024) mask[i] = 0u;
    __syncthreads();

    for (int e = 0; e < E; ++e) {
        const unsigned long long* ord = keys + (size_t)e * N_TOK;
        int count = 0, pos = 0;
        while (count < C && pos < N_TOK) {
            ulonglong2 a = *(const ulonglong2*)(ord + pos + tid * 4);
            ulonglong2 b = *(const ulonglong2*)(ord + pos + tid * 4 + 2);
            unsigned tk[4];
            tk[0] = (unsigned)a.x & 0xFFFFu;
            tk[1] = (unsigned)a.y & 0xFFFFu;
            tk[2] = (unsigned)b.x & 0xFFFFu;
            tk[3] = (unsigned)b.y & 0xFFFFu;
            int fl[4], cnt = 0;
            #pragma unroll
            for (int j = 0; j < 4; ++j) {
                fl[j] = 1 - (int)((mask[tk[j] >> 5] >> (tk[j] & 31)) & 1u);
                cnt += fl[j];
            }
            int inc = cnt;
            #pragma unroll
            for (int off = 1; off < 32; off <<= 1) {
                int n = __shfl_up_sync(0xffffffffu, inc, off);
                if (lane >= off) inc += n;
            }
            if (lane == 31) warp_sums[wid] = inc;
            int thr_excl = inc - cnt;
            __syncthreads();
            if (wid == 0) {
                int v = warp_sums[lane];
                #pragma unroll
                for (int off = 1; off < 32; off <<= 1) {
                    int n = __shfl_up_sync(0xffffffffu, v, off);
                    if (lane >= off) v += n;
                }
                warp_sums[lane] = v;
            }
            __syncthreads();
            int warp_excl = wid ? warp_sums[wid - 1] : 0;
            int total     = warp_sums[31];
            int remaining = C - count;
            int r = warp_excl + thr_excl;
            #pragma unroll
            for (int j = 0; j < 4; ++j) {
                if (fl[j]) {
                    if (r < remaining) {
                        sbe[e * C + count + r] = tk[j];
                        atomicOr(&mask[tk[j] >> 5], 1u << (tk[j] & 31));
                    }
                    ++r;
                }
            }
            count += min(total, remaining);
            pos += 4096;
            __syncthreads();
        }
    }
}

// ---------------------------------------------------------------------------
__global__ void pack_full(const unsigned* __restrict__ sbe,
                          float* __restrict__ out, int out_size)
{
    int i = blockIdx.x * blockDim.x + threadIdx.x;
    if (i >= out_size) return;
    float v;
    if (i < N_TOK)                v = (float)sbe[i];
    else if (i < N_TOK + 2 * E)   v = (float)C;
    else                          v = 1.0f;
    out[i] = v;
}

__global__ void pack_ones(float* __restrict__ out, int n)
{
    int i = blockIdx.x * blockDim.x + threadIdx.x;
    if (i < n) out[i] = 1.0f;
}

__global__ void pack_splits(float* __restrict__ out, int n)
{
    int i = blockIdx.x * blockDim.x + threadIdx.x;
    if (i < n) out[i] = (float)C;
}

// ---------------------------------------------------------------------------
extern "C" void kernel_launch(void* const* d_in, const int* in_sizes, int n_in,
                              void* d_out, int out_size)
{
    const float* F  = (const float*)d_in[0];
    const float* Wg = (const float*)d_in[1];
    if (n_in >= 2 && in_sizes[0] < in_sizes[1]) {
        F  = (const float*)d_in[1];
        Wg = (const float*)d_in[0];
    }

    unsigned long long* keys_a = nullptr;
    unsigned long long* keys_b = nullptr;
    int*      offsets = nullptr; unsigned* sbe = nullptr;
    unsigned char* temp = nullptr;
    cudaGetSymbolAddress((void**)&keys_a,  g_keys_a);
    cudaGetSymbolAddress((void**)&keys_b,  g_keys_b);
    cudaGetSymbolAddress((void**)&offsets, g_offsets);
    cudaGetSymbolAddress((void**)&sbe,     g_sbe);
    cudaGetSymbolAddress((void**)&temp,    g_temp);

    if (out_size == N_TOK) {
        pack_ones<<<(N_TOK + 255) / 256, 256>>>((float*)d_out, N_TOK);
        return;
    }
    if (out_size == 2 * E || out_size == E) {
        pack_splits<<<1, 256>>>((float*)d_out, out_size);
        return;
    }

    gemm_affin<<<N_TOK / 128, 256>>>(F, Wg, keys_a, offsets);

    // ONE global descending radix sort over bits [16,54): expert | score.
    // Full-chip onesweep parallelism vs. 64-CTA segmented kernel (R5: 64
    // blocks, occ 9%, DRAM 3.8% -> latency-bound, ~670us total).
    cub::DoubleBuffer<unsigned long long> dbuf(keys_a, keys_b);
    size_t temp_bytes = 0;
    cub::DeviceRadixSort::SortKeysDescending(
        nullptr, temp_bytes, dbuf, TOTAL, 16, 54);
    if (temp_bytes <= (size_t)(8u << 20)) {
        cub::DeviceRadixSort::SortKeysDescending(
            (void*)temp, temp_bytes, dbuf, TOTAL, 16, 54);
    } else {
        // Fallback: known-good segmented path (keys include expert bits, so
        // sorting bits [16,48) within segments is equivalent).
        size_t tb2 = 0;
        cub::DeviceSegmentedRadixSort::SortKeysDescending(
            nullptr, tb2, dbuf, TOTAL, E, offsets, offsets + 1, 16, 48);
        if (tb2 > (size_t)(8u << 20)) tb2 = (size_t)(8u << 20);
        cub::DeviceSegmentedRadixSort::SortKeysDescending(
            (void*)temp, tb2, dbuf, TOTAL, E, offsets, offsets + 1, 16, 48);
    }

    greedy_select<<<1, 1024>>>(dbuf.Current(), sbe);

    pack_full<<<(out_size + 255) / 256, 256>>>(sbe, (float*)d_out, out_size);
}